// round 2
// baseline (speedup 1.0000x reference)
#include <cuda_runtime.h>

// KANN_31379031064675 — 2-layer LagrangeKANN, staggered-sample warp scheme +
// f32x2 packed math + coalesced table build.

#define FULL_MASK 0xffffffffu
typedef unsigned long long u64;

__device__ __forceinline__ u64 f2pk(float lo, float hi) {
    u64 r; asm("mov.b64 %0, {%1, %2};" : "=l"(r) : "f"(lo), "f"(hi)); return r;
}
__device__ __forceinline__ void f2upk(float& lo, float& hi, u64 v) {
    asm("mov.b64 {%0, %1}, %2;" : "=f"(lo), "=f"(hi) : "l"(v));
}
__device__ __forceinline__ u64 f2add(u64 a, u64 b) {
    u64 r; asm("add.rn.f32x2 %0, %1, %2;" : "=l"(r) : "l"(a), "l"(b)); return r;
}
__device__ __forceinline__ u64 f2mul(u64 a, u64 b) {
    u64 r; asm("mul.rn.f32x2 %0, %1, %2;" : "=l"(r) : "l"(a), "l"(b)); return r;
}
__device__ __forceinline__ u64 f2fma(u64 a, u64 b, u64 c) {
    u64 r; asm("fma.rn.f32x2 %0, %1, %2, %3;" : "=l"(r) : "l"(a), "l"(b), "l"(c)); return r;
}

__global__ void __launch_bounds__(896, 1) kann_kernel(
    const float* __restrict__ x,
    const float* __restrict__ w_inner,
    const float* __restrict__ w_outer,
    float* __restrict__ out, int n)
{
    extern __shared__ float smem[];
    float* T1 = smem;           // u64 view: idx = e*128 + j*32 + lane  (pair k,k+32)
    float* T2 = smem + 16384;   // float4 view: idx = e*64 + k

    const int tid = threadIdx.x;

    // ---- coalesced table build (weights scanned linearly; STS scattered) ----
    // Lagrange constants folded in: c = {-9/16, 27/16, -27/16, 9/16}.
    for (int f = tid; f < 64 * 193; f += blockDim.x) {
        float v = w_inner[f];
        int k = f / 193;
        int nn = f - k * 193;
        int e = nn / 3;            // 0..64
        int j = nn - 3 * e;        // 0..2
        int kk = ((k & 31) << 1) | (k >> 5);
        if (nn < 192) {
            float cj = (j == 0) ? -0.5625f : (j == 1 ? 1.6875f : -1.6875f);
            T1[e * 256 + j * 64 + kk] = v * cj;
        }
        if (j == 0 && nn > 0) {
            T1[(e - 1) * 256 + 192 + kk] = v * 0.5625f;   // j=3 slot of previous element
        }
    }
    for (int f = tid; f < 64 * 193; f += blockDim.x) {
        float v = w_outer[f];
        int k = f / 193;
        int nn = f - k * 193;
        int e = nn / 3;
        int j = nn - 3 * e;
        if (nn < 192) {
            float cj = (j == 0) ? -0.5625f : (j == 1 ? 1.6875f : -1.6875f);
            T2[e * 256 + k * 4 + j] = v * cj;
        }
        if (j == 0 && nn > 0) {
            T2[(e - 1) * 256 + k * 4 + 3] = v * 0.5625f;
        }
    }
    __syncthreads();

    const u64* __restrict__ T1v = (const u64*)T1;
    const float4* __restrict__ T2v = (const float4*)T2;

    const int lane = tid & 31;
    const int wid = tid >> 5;
    const int nwarp = gridDim.x * (blockDim.x >> 5);
    const int gwarp = wid * gridDim.x + blockIdx.x;   // interleave: spread idle warps
    const int ngroups = n >> 5;

    // packed constants (live in registers across the loop)
    const u64 C192  = f2pk(192.0f, 192.0f);
    const u64 C1_3  = f2pk(1.0f / 3.0f, 1.0f / 3.0f);
    const u64 C2_3  = f2pk(2.0f / 3.0f, 2.0f / 3.0f);
    const u64 Cm2   = f2pk(-2.0f, -2.0f);
    const u64 Cm1   = f2pk(-1.0f, -1.0f);
    const u64 C1    = f2pk(1.0f, 1.0f);
    const u64 Cm1_3 = f2pk(-1.0f / 3.0f, -1.0f / 3.0f);

    for (int g = gwarp; g < ngroups; g += nwarp) {
        const int base = g << 5;
        float xcur = x[base + lane];
        float acc = 0.0f;

        #pragma unroll 1
        for (int i = 0; i < 32; ++i) {
            // lane l processes sample (l+i)&31 this iteration
            const float x0 = xcur;
            xcur = __shfl_sync(FULL_MASK, xcur, lane + 1);   // rotate for next iter

            // ---------- layer 1 (scalar, per-lane sample) ----------
            float xs = 192.0f * x0;
            float ef = floorf(xs * (1.0f / 3.0f));
            ef = fminf(fmaxf(ef, 0.0f), 63.0f);
            int e1 = (int)ef;
            float xt = fmaf(xs, (2.0f / 3.0f), fmaf(ef, -2.0f, -1.0f));
            float p = xt + 1.0f;
            float q = xt + (1.0f / 3.0f);
            float r = xt - (1.0f / 3.0f);
            float s = xt - 1.0f;
            float rs = r * s, pq = p * q;
            float ph0 = q * rs, ph1 = p * rs, ph2 = pq * s, ph3 = pq * r;

            const int b1 = (e1 << 7) + lane;
            u64 w0 = T1v[b1];
            u64 w1 = T1v[b1 + 32];
            u64 w2 = T1v[b1 + 64];
            u64 w3 = T1v[b1 + 96];
            u64 t12 = f2fma(f2pk(ph3, ph3), w3,
                      f2fma(f2pk(ph2, ph2), w2,
                      f2fma(f2pk(ph1, ph1), w1,
                      f2mul(f2pk(ph0, ph0), w0))));   // {t1 for width lane, width lane+32}

            // ---------- layer 2 (packed over the two widths) ----------
            u64 xs2 = f2mul(t12, C192);
            u64 ep2 = f2mul(xs2, C1_3);
            float eA, eB;
            f2upk(eA, eB, ep2);
            eA = fminf(fmaxf(floorf(eA), 0.0f), 63.0f);
            eB = fminf(fmaxf(floorf(eB), 0.0f), 63.0f);
            const int iA = (int)eA, iB = (int)eB;
            u64 xt2 = f2fma(xs2, C2_3, f2fma(f2pk(eA, eB), Cm2, Cm1));
            u64 p2 = f2add(xt2, C1);
            u64 q2 = f2add(xt2, C1_3);
            u64 r2 = f2add(xt2, Cm1_3);
            u64 s2 = f2add(xt2, Cm1);
            u64 rs2 = f2mul(r2, s2);
            u64 pq2 = f2mul(p2, q2);

            float4 wA = T2v[(iA << 6) + lane];
            float4 wB = T2v[(iB << 6) + 32 + lane];

            u64 g0 = f2mul(q2, rs2);
            u64 g1 = f2mul(p2, rs2);
            u64 g2 = f2mul(pq2, s2);
            u64 g3 = f2mul(pq2, r2);
            u64 d2 = f2fma(g3, f2pk(wA.w, wB.w),
                     f2fma(g2, f2pk(wA.z, wB.z),
                     f2fma(g1, f2pk(wA.y, wB.y),
                     f2mul(g0, f2pk(wA.x, wB.x)))));
            float tA2, tB2;
            f2upk(tA2, tB2, d2);

            // rotating accumulator: after 32 rotate-adds, lane l holds sample l's sum
            acc = __shfl_sync(FULL_MASK, acc + tA2 + tB2, lane + 1);
        }
        out[base + lane] = acc;
    }
}

extern "C" void kernel_launch(void* const* d_in, const int* in_sizes, int n_in,
                              void* d_out, int out_size) {
    const float* x  = (const float*)d_in[0];
    const float* wi = (const float*)d_in[1];
    const float* wo = (const float*)d_in[2];
    float* out = (float*)d_out;
    const int n = in_sizes[0];

    const int smem_bytes = 2 * 16384 * sizeof(float);  // 128 KB
    cudaFuncSetAttribute(kann_kernel, cudaFuncAttributeMaxDynamicSharedMemorySize,
                         smem_bytes);
    kann_kernel<<<148, 896, smem_bytes>>>(x, wi, wo, out, n);
}

// round 3
// speedup vs baseline: 1.7569x; 1.7569x over previous
#include <cuda_runtime.h>

// KANN_31379031064675 — 2-layer LagrangeKANN (64 width, order 3, 64 elements,
// 193 nodes, 131072 samples).
//
// Scheme: lane owns ONE sample for the whole group and walks the 64 widths
// over 32 iterations (pair w, w+32). Layer-1 element/xt computed once per
// group; accumulator is lane-local => ZERO shuffles in the main loop.
//
// Math: per (element,width) the Lagrange dot  sum_j phi_j(xt) W_j  is a cubic
// in xt; its monomial coefficients a0..a3 are precomputed into SMEM, so each
// layer evaluation is one table load + 3 FMA (Horner).
//
// SMEM layouts (both conflict-free for per-lane element indices, since the
// element stride is 1024 B ≡ 0 mod 128 B):
//   T1: u64 idx = e*128 + c*32 + w     -> pair (a_c[w], a_c[w+32]), LDS.64
//   T2: float4 idx = e*64 + k          -> {a0,a1,a2,a3},            LDS.128

typedef unsigned long long u64;

__global__ void __launch_bounds__(896, 1) kann_kernel(
    const float* __restrict__ x,
    const float* __restrict__ w_inner,
    const float* __restrict__ w_outer,
    float* __restrict__ out, int n)
{
    extern __shared__ float smem[];
    float* T1 = smem;           // 16384 floats
    float* T2 = smem + 16384;   // 16384 floats

    const int tid = threadIdx.x;
    const int nt = blockDim.x;

    // ================= table build =================
    // Lagrange->monomial conversion, constants c_j = {-9/16,27/16,-27/16,9/16}
    // folded. Numerators expanded about nodes {-1,-1/3,1/3,1}:
    //   a3 = u0+u1+u2+u3
    //   a2 = (u3-u0) + (u2-u1)/3
    //   a1 = -(u1+u2) - (u0+u3)/9
    //   a0 = (u1-u2)/3 + (u0-u3)/9        with u_j = c_j * W_j
    float a[5][4];

    // ---- layer 1: stage coalesced, gather bank-clean (stride 193 = odd) ----
    for (int f = tid; f < 64 * 193; f += nt) T1[f] = w_inner[f];
    __syncthreads();
    #pragma unroll
    for (int r = 0; r < 5; ++r) {
        int f = tid + r * nt;
        if (f < 4096) {
            int k = f & 63, e = f >> 6;
            const float* wp = T1 + k * 193 + 3 * e;
            float u0 = -0.5625f * wp[0], u1 = 1.6875f * wp[1];
            float u2 = -1.6875f * wp[2], u3 = 0.5625f * wp[3];
            a[r][3] = (u0 + u1) + (u2 + u3);
            a[r][2] = (u3 - u0) + (1.0f / 3.0f) * (u2 - u1);
            a[r][1] = -(u1 + u2) - (1.0f / 9.0f) * (u0 + u3);
            a[r][0] = (1.0f / 3.0f) * (u1 - u2) + (1.0f / 9.0f) * (u0 - u3);
        }
    }
    __syncthreads();
    #pragma unroll
    for (int r = 0; r < 5; ++r) {
        int f = tid + r * nt;
        if (f < 4096) {
            int k = f & 63, e = f >> 6;
            int base = e * 256 + 2 * (k & 31) + (k >> 5);   // <=2-way STS conflicts
            T1[base]       = a[r][0];
            T1[base + 64]  = a[r][1];
            T1[base + 128] = a[r][2];
            T1[base + 192] = a[r][3];
        }
    }
    // ---- layer 2 ----
    for (int f = tid; f < 64 * 193; f += nt) T2[f] = w_outer[f];
    __syncthreads();
    #pragma unroll
    for (int r = 0; r < 5; ++r) {
        int f = tid + r * nt;
        if (f < 4096) {
            int k = f & 63, e = f >> 6;
            const float* wp = T2 + k * 193 + 3 * e;
            float u0 = -0.5625f * wp[0], u1 = 1.6875f * wp[1];
            float u2 = -1.6875f * wp[2], u3 = 0.5625f * wp[3];
            a[r][3] = (u0 + u1) + (u2 + u3);
            a[r][2] = (u3 - u0) + (1.0f / 3.0f) * (u2 - u1);
            a[r][1] = -(u1 + u2) - (1.0f / 9.0f) * (u0 + u3);
            a[r][0] = (1.0f / 3.0f) * (u1 - u2) + (1.0f / 9.0f) * (u0 - u3);
        }
    }
    __syncthreads();
    #pragma unroll
    for (int r = 0; r < 5; ++r) {
        int f = tid + r * nt;
        if (f < 4096) {
            int k = f & 63, e = f >> 6;
            float4* dst = (float4*)(T2 + e * 256 + k * 4);  // STS.128, phase-clean
            *dst = make_float4(a[r][0], a[r][1], a[r][2], a[r][3]);
        }
    }
    __syncthreads();

    // ================= main loop =================
    const u64* __restrict__ T1v = (const u64*)T1;
    const float4* __restrict__ T2v = (const float4*)T2;

    const int lane = tid & 31;
    const int wid = tid >> 5;
    const int nwarp = gridDim.x * (nt >> 5);
    const int gwarp = wid * gridDim.x + blockIdx.x;   // spread tail-idle warps
    const int ngroups = n >> 5;

    for (int g = gwarp; g < ngroups; g += nwarp) {
        const int base = g << 5;
        const float xv = x[base + lane];

        // layer-1 sample params: once per group (lane's sample is fixed)
        float ef = floorf(64.0f * xv);
        ef = fminf(fmaxf(ef, 0.0f), 63.0f);
        const float xt1 = fmaf(xv, 128.0f, fmaf(ef, -2.0f, -1.0f));
        const int b1 = ((int)ef) << 7;     // u64 index base (= e*128)

        float acc = 0.0f;
        int w = lane;
        #pragma unroll 4
        for (int i = 0; i < 32; ++i) {
            // layer 1: Horner over widths (w, w+32), shared xt1
            const float2 c0 = *(const float2*)(T1v + b1 + w);
            const float2 c1 = *(const float2*)(T1v + b1 + 32 + w);
            const float2 c2 = *(const float2*)(T1v + b1 + 64 + w);
            const float2 c3 = *(const float2*)(T1v + b1 + 96 + w);
            const float tA = fmaf(fmaf(fmaf(c3.x, xt1, c2.x), xt1, c1.x), xt1, c0.x);
            const float tB = fmaf(fmaf(fmaf(c3.y, xt1, c2.y), xt1, c1.y), xt1, c0.y);

            // layer 2, width w
            float eA = fminf(fmaxf(floorf(64.0f * tA), 0.0f), 63.0f);
            const float xtA = fmaf(tA, 128.0f, fmaf(eA, -2.0f, -1.0f));
            const float4 dA = T2v[(((int)eA) << 6) + w];
            const float vA = fmaf(fmaf(fmaf(dA.w, xtA, dA.z), xtA, dA.y), xtA, dA.x);

            // layer 2, width w+32
            float eB = fminf(fmaxf(floorf(64.0f * tB), 0.0f), 63.0f);
            const float xtB = fmaf(tB, 128.0f, fmaf(eB, -2.0f, -1.0f));
            const float4 dB = T2v[(((int)eB) << 6) + 32 + w];
            const float vB = fmaf(fmaf(fmaf(dB.w, xtB, dB.z), xtB, dB.y), xtB, dB.x);

            acc += vA + vB;
            w = (w + 1) & 31;
        }
        out[base + lane] = acc;
    }
}

extern "C" void kernel_launch(void* const* d_in, const int* in_sizes, int n_in,
                              void* d_out, int out_size) {
    const float* x  = (const float*)d_in[0];
    const float* wi = (const float*)d_in[1];
    const float* wo = (const float*)d_in[2];
    float* out = (float*)d_out;
    const int n = in_sizes[0];

    const int smem_bytes = 2 * 16384 * sizeof(float);  // 128 KB
    cudaFuncSetAttribute(kann_kernel, cudaFuncAttributeMaxDynamicSharedMemorySize,
                         smem_bytes);
    kann_kernel<<<148, 896, smem_bytes>>>(x, wi, wo, out, n);
}

// round 4
// speedup vs baseline: 1.8733x; 1.0663x over previous
#include <cuda_runtime.h>

// KANN_31379031064675 — 2-layer LagrangeKANN.
// Lane owns one sample per 32-group; walks widths (w, w+32) over 32 iters.
// Layer 1: compact Lagrange table (193x32 float2, 49.4 KB); basis phi0..3
//          computed ONCE per group (sample fixed per lane) -> 4 LDS.64 + 8 FMA/iter.
// Layer 2: expanded monomial table (64 KB), 3-FMA Horner on the critical chain.
// Total smem 112.3 KB -> 1024-thread block, 32 warps/SM (occ 50%).

__global__ void __launch_bounds__(1024, 1) kann_kernel(
    const float* __restrict__ x,
    const float* __restrict__ w_inner,
    const float* __restrict__ w_outer,
    float* __restrict__ out, int n)
{
    extern __shared__ float smem[];
    // [0, 12352)      : T1 compact, float2 idx = jabs*32 + p  -> {W[p][jabs], W[p+32][jabs]}
    // [12352, 28736)  : T2 expanded monomial, float4 idx = e*64 + k
    float2* T1v = (float2*)smem;
    float* T2f = smem + 12352;
    float* S   = smem + 12352;   // staging scratch (reused, 16384 >= 12352 floats)

    const int tid = threadIdx.x;
    const int nt = blockDim.x;

    // ---------------- build ----------------
    // Phase A: stage w_inner coalesced into scratch
    for (int f = tid; f < 12352; f += nt) S[f] = w_inner[f];
    __syncthreads();
    // Phase B: gather into compact T1 (bank-clean: stride 193 odd)
    for (int idx = tid; idx < 6176; idx += nt) {
        int jabs = idx >> 5, p = idx & 31;
        T1v[idx] = make_float2(S[p * 193 + jabs], S[(p + 32) * 193 + jabs]);
    }
    __syncthreads();
    // Phase C: stage w_outer into scratch
    for (int f = tid; f < 12352; f += nt) S[f] = w_outer[f];
    __syncthreads();
    // Phase D: read quads into registers (scratch shares space with final T2)
    float a[4][4];
    #pragma unroll
    for (int r = 0; r < 4; ++r) {
        int f = tid + r * nt;
        if (f < 4096) {
            int k = f & 63, e = f >> 6;
            const float* wp = S + k * 193 + 3 * e;
            float u0 = -0.5625f * wp[0], u1 = 1.6875f * wp[1];
            float u2 = -1.6875f * wp[2], u3 = 0.5625f * wp[3];
            a[r][3] = (u0 + u1) + (u2 + u3);
            a[r][2] = (u3 - u0) + (1.0f / 3.0f) * (u2 - u1);
            a[r][1] = -(u1 + u2) - (1.0f / 9.0f) * (u0 + u3);
            a[r][0] = (1.0f / 3.0f) * (u1 - u2) + (1.0f / 9.0f) * (u0 - u3);
        }
    }
    __syncthreads();
    // Phase E: write expanded monomial T2 (STS.128, phase-clean)
    #pragma unroll
    for (int r = 0; r < 4; ++r) {
        int f = tid + r * nt;
        if (f < 4096) {
            int k = f & 63, e = f >> 6;
            ((float4*)T2f)[e * 64 + k] = make_float4(a[r][0], a[r][1], a[r][2], a[r][3]);
        }
    }
    __syncthreads();

    // ---------------- main ----------------
    const float4* __restrict__ T2v = (const float4*)T2f;

    const int lane = tid & 31;
    const int wid = tid >> 5;
    const int nwarp = gridDim.x * (nt >> 5);
    const int gwarp = wid * gridDim.x + blockIdx.x;
    const int ngroups = n >> 5;

    for (int g = gwarp; g < ngroups; g += nwarp) {
        const int base = g << 5;
        const float xv = x[base + lane];

        // per-group layer-1 params (sample fixed per lane)
        float u = 64.0f * xv;
        float ef = fminf(fmaxf(floorf(u), 0.0f), 63.0f);
        const float xt = fmaf(xv, 128.0f, fmaf(ef, -2.0f, -1.0f));
        const int b1 = ((int)ef) * 96;   // float2 index base = 3*e*32

        // Lagrange basis with c_j folded, once per group
        const float p = xt + 1.0f;
        const float q = xt + (1.0f / 3.0f);
        const float r = xt - (1.0f / 3.0f);
        const float s = xt - 1.0f;
        const float rs = r * s, pq = p * q;
        const float ph0 = -0.5625f * (q * rs);
        const float ph1 =  1.6875f * (p * rs);
        const float ph2 = -1.6875f * (pq * s);
        const float ph3 =  0.5625f * (pq * r);

        float acc = 0.0f;
        #pragma unroll 4
        for (int i = 0; i < 32; ++i) {
            const int w = (lane + i) & 31;

            // layer 1: 4 LDS.64 + 8 FMA, widths (w, w+32)
            const float2 w0 = T1v[b1 + w];
            const float2 w1 = T1v[b1 + 32 + w];
            const float2 w2 = T1v[b1 + 64 + w];
            const float2 w3 = T1v[b1 + 96 + w];
            const float tA = fmaf(ph3, w3.x, fmaf(ph2, w2.x, fmaf(ph1, w1.x, ph0 * w0.x)));
            const float tB = fmaf(ph3, w3.y, fmaf(ph2, w2.y, fmaf(ph1, w1.y, ph0 * w0.y)));

            // layer 2, width w
            float uA = 64.0f * tA;
            float eA = fminf(fmaxf(floorf(uA), 0.0f), 63.0f);
            const float xtA = fmaf(tA, 128.0f, fmaf(eA, -2.0f, -1.0f));
            const float4 dA = T2v[(((int)eA) << 6) + w];
            const float vA = fmaf(fmaf(fmaf(dA.w, xtA, dA.z), xtA, dA.y), xtA, dA.x);

            // layer 2, width w+32
            float uB = 64.0f * tB;
            float eB = fminf(fmaxf(floorf(uB), 0.0f), 63.0f);
            const float xtB = fmaf(tB, 128.0f, fmaf(eB, -2.0f, -1.0f));
            const float4 dB = T2v[(((int)eB) << 6) + 32 + w];
            const float vB = fmaf(fmaf(fmaf(dB.w, xtB, dB.z), xtB, dB.y), xtB, dB.x);

            acc += vA + vB;
        }
        out[base + lane] = acc;
    }
}

extern "C" void kernel_launch(void* const* d_in, const int* in_sizes, int n_in,
                              void* d_out, int out_size) {
    const float* x  = (const float*)d_in[0];
    const float* wi = (const float*)d_in[1];
    const float* wo = (const float*)d_in[2];
    float* out = (float*)d_out;
    const int n = in_sizes[0];

    const int smem_bytes = 28736 * sizeof(float);  // 112.25 KB
    cudaFuncSetAttribute(kann_kernel, cudaFuncAttributeMaxDynamicSharedMemorySize,
                         smem_bytes);
    kann_kernel<<<148, 1024, smem_bytes>>>(x, wi, wo, out, n);
}